// round 2
// baseline (speedup 1.0000x reference)
#include <cuda_runtime.h>
#include <math.h>

#define BB 16
#define LATD 8
#define NPTS 500000
#define XSZ 256
#define HSPEC 129   // XSZ/2 + 1
#define IMG_ELEMS (BB*XSZ*XSZ)

// ---------------- scratch (device globals; no allocation allowed) ----------
__device__ float  g_img[IMG_ELEMS];                 // 4 MB accumulation image
__device__ float  g_blur[IMG_ELEMS];                // 4 MB y-blurred image
__device__ float2 g_spec[BB*XSZ*HSPEC];             // 4.2 MB half-spectrum
__device__ float  g_params[BB][16];                 // R rows(6), shifts(2), h(8)

// Gaussian kernel (sigma=1, radius=3), normalized (double-derived constants)
__device__ __constant__ float c_gk[7] = {
    0.0044330481f, 0.0540055826f, 0.2420362294f, 0.3990502730f,
    0.2420362294f, 0.0540055826f, 0.0044330481f
};

// ---------------- kernels ---------------------------------------------------

__global__ void zero_kernel() {
    int i = blockIdx.x * blockDim.x + threadIdx.x;
    if (i < IMG_ELEMS) g_img[i] = 0.0f;
}

__global__ void prep_kernel(const float* __restrict__ rows,
                            const float* __restrict__ shifts,
                            const float* __restrict__ latent,
                            const float* __restrict__ W0, const float* __restrict__ b0,
                            const float* __restrict__ W1, const float* __restrict__ b1,
                            const float* __restrict__ W2, const float* __restrict__ b2,
                            const float* __restrict__ W3, const float* __restrict__ b3) {
    int b = threadIdx.x;
    if (b >= BB) return;
    // f32 trig (libdevice, same as XLA), explicit no-FMA products in XLA order
    float rot  = rows[b*3+0];
    float tilt = rows[b*3+1];
    float psi  = rows[b*3+2];
    float ca = cosf(rot),  sa = sinf(rot);
    float cb = cosf(tilt), sb = sinf(tilt);
    float cg = cosf(psi),  sg = sinf(psi);
    float cgcb = __fmul_rn(cg, cb);
    float sgcb = __fmul_rn(sg, cb);
    // R00 = cg*cb*ca - sg*sa ; R01 = cg*cb*sa + sg*ca ; R02 = -cg*sb
    g_params[b][0] = __fsub_rn(__fmul_rn(cgcb, ca), __fmul_rn(sg, sa));
    g_params[b][1] = __fadd_rn(__fmul_rn(cgcb, sa), __fmul_rn(sg, ca));
    g_params[b][2] = -__fmul_rn(cg, sb);
    // R10 = -sg*cb*ca - cg*sa ; R11 = -sg*cb*sa + cg*ca ; R12 = sg*sb
    g_params[b][3] = __fsub_rn(__fmul_rn(-sgcb, ca), __fmul_rn(cg, sa));
    g_params[b][4] = __fadd_rn(__fmul_rn(-sgcb, sa), __fmul_rn(cg, ca));
    g_params[b][5] = __fmul_rn(sg, sb);
    g_params[b][6] = shifts[b*2+0];
    g_params[b][7] = shifts[b*2+1];

    // tiny SIREN MLP: h = sin(30*(latent@W0+b0)); 3x residual sin layers
    float h[LATD];
    #pragma unroll
    for (int j = 0; j < LATD; j++) {
        float z = b0[j];
        #pragma unroll
        for (int l = 0; l < LATD; l++) z += latent[b*LATD+l] * W0[l*LATD+j];
        h[j] = sinf(30.0f * z);
    }
    const float* Ws[3] = {W1, W2, W3};
    const float* bs[3] = {b1, b2, b3};
    for (int L = 0; L < 3; L++) {
        float t[LATD];
        #pragma unroll
        for (int j = 0; j < LATD; j++) {
            float z = bs[L][j];
            #pragma unroll
            for (int l = 0; l < LATD; l++) z += h[l] * Ws[L][l*LATD+j];
            t[j] = sinf(z);
        }
        #pragma unroll
        for (int j = 0; j < LATD; j++) h[j] += t[j];
    }
    #pragma unroll
    for (int j = 0; j < LATD; j++) g_params[b][8+j] = h[j];
}

__global__ void scatter_kernel(const float* __restrict__ coords,
                               const float* __restrict__ values,
                               const float* __restrict__ Wd,
                               const float* __restrict__ bd) {
    __shared__ float sp[BB][16];
    int t = threadIdx.x;
    if (t < BB*16) ((float*)sp)[t] = ((const float*)g_params)[t];
    __syncthreads();

    int n = blockIdx.x * blockDim.x + t;
    if (n >= NPTS) return;

    float cx = coords[n*3+0];
    float cy = coords[n*3+1];
    float cz = coords[n*3+2];
    float v   = values[n];
    float bdn = bd[n];
    float wd[LATD];
    #pragma unroll
    for (int l = 0; l < LATD; l++) wd[l] = Wd[l*NPTS + n];

    #pragma unroll
    for (int b = 0; b < BB; b++) {
        // pinned ascending FMA chain (cuBLAS-style) for the K=3 contraction
        float x = __fmul_rn(sp[b][0], cx);
        x = __fmaf_rn(sp[b][1], cy, x);
        x = __fmaf_rn(sp[b][2], cz, x);
        float y = __fmul_rn(sp[b][3], cx);
        y = __fmaf_rn(sp[b][4], cy, y);
        y = __fmaf_rn(sp[b][5], cz, y);
        // match reference ordering: round((x + shift) + 128), round->clip->int
        float fx = rintf(__fadd_rn(__fadd_rn(x, sp[b][6]), 128.0f));
        float fy = rintf(__fadd_rn(__fadd_rn(y, sp[b][7]), 128.0f));
        fx = fminf(fmaxf(fx, 0.0f), 255.0f);
        fy = fminf(fmaxf(fy, 0.0f), 255.0f);
        int ix = (int)fx;
        int iy = (int)fy;
        float dot = sp[b][8] * wd[0];
        #pragma unroll
        for (int l = 1; l < LATD; l++) dot += sp[b][8+l] * wd[l];
        float val = v + (dot + bdn);
        atomicAdd(&g_img[(b << 16) | (iy << 8) | ix], val);
    }
}

__global__ void blur_y_kernel() {
    int idx = blockIdx.x * blockDim.x + threadIdx.x;
    if (idx >= IMG_ELEMS) return;
    int y = (idx >> 8) & 255;
    float acc = 0.0f;
    #pragma unroll
    for (int d = -3; d <= 3; d++) {
        int yy = y + d;
        if (yy >= 0 && yy < XSZ) acc += c_gk[d+3] * g_img[idx + (d << 8)];
    }
    g_blur[idx] = acc;
}

// ---- shared-memory radix-2 FFT (length 256, 64 threads, DIT, brev input) ----

__device__ __forceinline__ void init_tw(float2* tw, int tid) {
    for (int k = tid; k < 128; k += 64) {
        double s, c;
        sincos(-3.14159265358979323846 * (double)k / 128.0, &s, &c);
        tw[k] = make_float2((float)c, (float)s);   // exp(-i*pi*k/128)
    }
}

__device__ __forceinline__ void fft256(float2* s, const float2* tw, int tid, bool inverse) {
    #pragma unroll
    for (int st = 0; st < 8; st++) {
        __syncthreads();
        int half = 1 << st;
        #pragma unroll
        for (int q = 0; q < 2; q++) {
            int j   = tid + (q << 6);
            int pos = j & (half - 1);
            int k   = ((j >> st) << (st + 1)) + pos;
            float2 w = tw[pos << (7 - st)];
            float wr = w.x;
            float wi = inverse ? -w.y : w.y;
            float2 u  = s[k];
            float2 vv = s[k + half];
            float tr = wr*vv.x - wi*vv.y;
            float ti = wr*vv.y + wi*vv.x;
            s[k]        = make_float2(u.x + tr, u.y + ti);
            s[k + half] = make_float2(u.x - tr, u.y - ti);
        }
    }
    __syncthreads();
}

#define BREV8(i) (__brev((unsigned)(i)) >> 24)

// x-blur fused + forward row rFFT: g_blur row -> g_spec[b][y][0..128]
__global__ void fftrow_kernel() {
    __shared__ float  row[XSZ];
    __shared__ float2 s[XSZ];
    __shared__ float2 tw[128];
    int tid = threadIdx.x;
    int br  = blockIdx.x;              // b*256 + y
    init_tw(tw, tid);
    for (int i = tid; i < XSZ; i += 64) row[i] = g_blur[br*XSZ + i];
    __syncthreads();
    for (int i = tid; i < XSZ; i += 64) {
        float acc = 0.0f;
        #pragma unroll
        for (int d = -3; d <= 3; d++) {
            int xx = i + d;
            if (xx >= 0 && xx < XSZ) acc += c_gk[d+3] * row[xx];
        }
        s[BREV8(i)] = make_float2(acc, 0.0f);
    }
    fft256(s, tw, tid, false);
    for (int k = tid; k < HSPEC; k += 64) g_spec[br*HSPEC + k] = s[k];
}

// forward y FFT, multiply CTF, inverse y FFT (per half-spectrum column kx)
__global__ void fftcol_kernel(const float* __restrict__ ctf) {
    __shared__ float2 s[XSZ];
    __shared__ float2 t2[XSZ];
    __shared__ float2 tw[128];
    int tid = threadIdx.x;
    int b  = blockIdx.x / HSPEC;
    int kx = blockIdx.x - b * HSPEC;
    init_tw(tw, tid);
    long base = (long)b * XSZ * HSPEC + kx;
    for (int y = tid; y < XSZ; y += 64)
        s[BREV8(y)] = g_spec[base + (long)y * HSPEC];
    fft256(s, tw, tid, false);
    for (int ky = tid; ky < XSZ; ky += 64) {
        float c = ctf[(b*XSZ + ky)*HSPEC + kx];
        float2 vv = s[ky];
        t2[BREV8(ky)] = make_float2(vv.x * c, vv.y * c);
    }
    fft256(t2, tw, tid, true);
    for (int y = tid; y < XSZ; y += 64)
        g_spec[base + (long)y * HSPEC] = t2[y];
}

// inverse row rFFT: Hermitian extend 129 -> 256, ifft, write real * 1/65536
__global__ void ifftrow_kernel(float* __restrict__ out) {
    __shared__ float2 s[XSZ];
    __shared__ float2 tw[128];
    int tid = threadIdx.x;
    int br  = blockIdx.x;              // b*256 + y
    init_tw(tw, tid);
    for (int k = tid; k < HSPEC; k += 64) {
        float2 vv = g_spec[br*HSPEC + k];
        s[BREV8(k)] = vv;
        if (k >= 1 && k <= 127) s[BREV8(256 - k)] = make_float2(vv.x, -vv.y);
    }
    fft256(s, tw, tid, true);
    const float scale = 1.0f / 65536.0f;
    for (int i = tid; i < XSZ; i += 64) out[br*XSZ + i] = s[i].x * scale;
}

// ---------------- launch -----------------------------------------------------

extern "C" void kernel_launch(void* const* d_in, const int* in_sizes, int n_in,
                              void* d_out, int out_size) {
    const float* rows   = (const float*)d_in[0];
    const float* shifts = (const float*)d_in[1];
    const float* latent = (const float*)d_in[2];
    const float* coords = (const float*)d_in[3];
    const float* values = (const float*)d_in[4];
    const float* W0 = (const float*)d_in[5];
    const float* b0 = (const float*)d_in[6];
    const float* W1 = (const float*)d_in[7];
    const float* b1 = (const float*)d_in[8];
    const float* W2 = (const float*)d_in[9];
    const float* b2 = (const float*)d_in[10];
    const float* W3 = (const float*)d_in[11];
    const float* b3 = (const float*)d_in[12];
    const float* Wd = (const float*)d_in[13];
    const float* bd = (const float*)d_in[14];
    const float* ctf = (const float*)d_in[15];
    float* out = (float*)d_out;

    zero_kernel<<<(IMG_ELEMS + 255)/256, 256>>>();
    prep_kernel<<<1, 32>>>(rows, shifts, latent, W0, b0, W1, b1, W2, b2, W3, b3);
    scatter_kernel<<<(NPTS + 255)/256, 256>>>(coords, values, Wd, bd);
    blur_y_kernel<<<(IMG_ELEMS + 255)/256, 256>>>();
    fftrow_kernel<<<BB*XSZ, 64>>>();
    fftcol_kernel<<<BB*HSPEC, 64>>>(ctf);
    ifftrow_kernel<<<BB*XSZ, 64>>>(out);
}

// round 3
// speedup vs baseline: 1.5080x; 1.5080x over previous
#include <cuda_runtime.h>
#include <math.h>

#define BB 16
#define LATD 8
#define NPTS 500000
#define XSZ 256
#define HSPEC 129   // XSZ/2 + 1
#define IMG_ELEMS (BB*XSZ*XSZ)

// ---------------- scratch (device globals; no allocation allowed) ----------
__device__ float  g_img[IMG_ELEMS];                 // 4 MB accumulation image
__device__ float2 g_spec[BB*XSZ*HSPEC];             // 8.25 MB half-spectrum
__device__ float  g_params[BB][16];                 // R rows(6), shifts(2), h(8)
__device__ float2 g_tw[128];                        // FFT twiddles (double-derived)

// Gaussian kernel (sigma=1, radius=3), normalized (double-derived constants)
__device__ __constant__ float c_gk[7] = {
    0.0044330481f, 0.0540055826f, 0.2420362294f, 0.3990502730f,
    0.2420362294f, 0.0540055826f, 0.0044330481f
};

// ---------------- kernels ---------------------------------------------------

__global__ void zero_kernel() {
    int i = blockIdx.x * blockDim.x + threadIdx.x;
    ((float4*)g_img)[i] = make_float4(0.f, 0.f, 0.f, 0.f);
}

__global__ void prep_kernel(const float* __restrict__ rows,
                            const float* __restrict__ shifts,
                            const float* __restrict__ latent,
                            const float* __restrict__ W0, const float* __restrict__ b0,
                            const float* __restrict__ W1, const float* __restrict__ b1,
                            const float* __restrict__ W2, const float* __restrict__ b2,
                            const float* __restrict__ W3, const float* __restrict__ b3) {
    int tid = threadIdx.x;
    // twiddle table, computed once per launch (double trig, bit-identical to R2)
    if (tid < 128) {
        double s, c;
        sincos(-3.14159265358979323846 * (double)tid / 128.0, &s, &c);
        g_tw[tid] = make_float2((float)c, (float)s);
    }
    int b = tid;
    if (b >= BB) return;
    // ---- FROZEN position-path arithmetic (do not modify) ----
    float rot  = rows[b*3+0];
    float tilt = rows[b*3+1];
    float psi  = rows[b*3+2];
    float ca = cosf(rot),  sa = sinf(rot);
    float cb = cosf(tilt), sb = sinf(tilt);
    float cg = cosf(psi),  sg = sinf(psi);
    float cgcb = __fmul_rn(cg, cb);
    float sgcb = __fmul_rn(sg, cb);
    g_params[b][0] = __fsub_rn(__fmul_rn(cgcb, ca), __fmul_rn(sg, sa));
    g_params[b][1] = __fadd_rn(__fmul_rn(cgcb, sa), __fmul_rn(sg, ca));
    g_params[b][2] = -__fmul_rn(cg, sb);
    g_params[b][3] = __fsub_rn(__fmul_rn(-sgcb, ca), __fmul_rn(cg, sa));
    g_params[b][4] = __fadd_rn(__fmul_rn(-sgcb, sa), __fmul_rn(cg, ca));
    g_params[b][5] = __fmul_rn(sg, sb);
    g_params[b][6] = shifts[b*2+0];
    g_params[b][7] = shifts[b*2+1];

    float h[LATD];
    #pragma unroll
    for (int j = 0; j < LATD; j++) {
        float z = b0[j];
        #pragma unroll
        for (int l = 0; l < LATD; l++) z += latent[b*LATD+l] * W0[l*LATD+j];
        h[j] = sinf(30.0f * z);
    }
    const float* Ws[3] = {W1, W2, W3};
    const float* bs[3] = {b1, b2, b3};
    for (int L = 0; L < 3; L++) {
        float t[LATD];
        #pragma unroll
        for (int j = 0; j < LATD; j++) {
            float z = bs[L][j];
            #pragma unroll
            for (int l = 0; l < LATD; l++) z += h[l] * Ws[L][l*LATD+j];
            t[j] = sinf(z);
        }
        #pragma unroll
        for (int j = 0; j < LATD; j++) h[j] += t[j];
    }
    #pragma unroll
    for (int j = 0; j < LATD; j++) g_params[b][8+j] = h[j];
}

__global__ void scatter_kernel(const float* __restrict__ coords,
                               const float* __restrict__ values,
                               const float* __restrict__ Wd,
                               const float* __restrict__ bd) {
    __shared__ float sp[BB][16];
    __shared__ float sc[768];          // staged coords for this block (coalesced)
    int t = threadIdx.x;
    if (t < BB*16) ((float*)sp)[t] = ((const float*)g_params)[t];
    int base = blockIdx.x * 256 * 3;
    #pragma unroll
    for (int f = 0; f < 3; f++) {
        int g = base + t + f*256;
        sc[t + f*256] = (g < NPTS*3) ? coords[g] : 0.0f;
    }
    __syncthreads();

    int n = blockIdx.x * blockDim.x + t;
    if (n >= NPTS) return;

    float cx = sc[t*3+0];
    float cy = sc[t*3+1];
    float cz = sc[t*3+2];
    float v   = values[n];
    float bdn = bd[n];
    float wd[LATD];
    #pragma unroll
    for (int l = 0; l < LATD; l++) wd[l] = Wd[l*NPTS + n];

    #pragma unroll
    for (int b = 0; b < BB; b++) {
        // ---- FROZEN position-path arithmetic (do not modify) ----
        float x = __fmul_rn(sp[b][0], cx);
        x = __fmaf_rn(sp[b][1], cy, x);
        x = __fmaf_rn(sp[b][2], cz, x);
        float y = __fmul_rn(sp[b][3], cx);
        y = __fmaf_rn(sp[b][4], cy, y);
        y = __fmaf_rn(sp[b][5], cz, y);
        float fx = rintf(__fadd_rn(__fadd_rn(x, sp[b][6]), 128.0f));
        float fy = rintf(__fadd_rn(__fadd_rn(y, sp[b][7]), 128.0f));
        fx = fminf(fmaxf(fx, 0.0f), 255.0f);
        fy = fminf(fmaxf(fy, 0.0f), 255.0f);
        int ix = (int)fx;
        int iy = (int)fy;
        float dot = sp[b][8] * wd[0];
        #pragma unroll
        for (int l = 1; l < LATD; l++) dot += sp[b][8+l] * wd[l];
        float val = v + (dot + bdn);
        atomicAdd(&g_img[(b << 16) | (iy << 8) | ix], val);
    }
}

// ---- shared-memory radix-2 FFT (length 256, 64 lanes per sub-FFT) ----------
// __syncthreads inside is block-wide; all sub-FFTs in the block run the same
// stage schedule, so this is correct for multiple FFTs per block.

__device__ __forceinline__ void fft256(float2* s, const float2* tw, int lane, bool inverse) {
    #pragma unroll
    for (int st = 0; st < 8; st++) {
        __syncthreads();
        int half = 1 << st;
        #pragma unroll
        for (int q = 0; q < 2; q++) {
            int j   = lane + (q << 6);
            int pos = j & (half - 1);
            int k   = ((j >> st) << (st + 1)) + pos;
            float2 w = tw[pos << (7 - st)];
            float wr = w.x;
            float wi = inverse ? -w.y : w.y;
            float2 u  = s[k];
            float2 vv = s[k + half];
            float tr = wr*vv.x - wi*vv.y;
            float ti = wr*vv.y + wi*vv.x;
            s[k]        = make_float2(u.x + tr, u.y + ti);
            s[k + half] = make_float2(u.x - tr, u.y - ti);
        }
    }
    __syncthreads();
}

#define BREV8(i) (__brev((unsigned)(i)) >> 24)

// fused y-blur + x-blur + forward row rFFT: g_img -> g_spec[b][y][0..128]
// 4 rows per block, 256 threads.
__global__ void fftrow_kernel() {
    __shared__ float  rowb[4][XSZ];
    __shared__ float2 s[4][XSZ];
    __shared__ float2 tw[128];
    int tid  = threadIdx.x;
    int sub  = tid >> 6;
    int lane = tid & 63;
    if (tid < 128) tw[tid] = g_tw[tid];
    int br = blockIdx.x * 4 + sub;     // b*256 + y
    int b  = br >> 8;
    int y  = br & 255;
    // y-blur (same arithmetic order as R2 blur_y_kernel)
    for (int i = lane; i < XSZ; i += 64) {
        float acc = 0.0f;
        #pragma unroll
        for (int d = -3; d <= 3; d++) {
            int yy = y + d;
            if (yy >= 0 && yy < XSZ) acc += c_gk[d+3] * g_img[((b << 8) | yy) * XSZ + i];
        }
        rowb[sub][i] = acc;
    }
    __syncthreads();
    // x-blur (same order as R2 fftrow)
    for (int i = lane; i < XSZ; i += 64) {
        float acc = 0.0f;
        #pragma unroll
        for (int d = -3; d <= 3; d++) {
            int xx = i + d;
            if (xx >= 0 && xx < XSZ) acc += c_gk[d+3] * rowb[sub][xx];
        }
        s[sub][BREV8(i)] = make_float2(acc, 0.0f);
    }
    fft256(s[sub], tw, lane, false);
    for (int k = lane; k < HSPEC; k += 64) g_spec[br*HSPEC + k] = s[sub][k];
}

// forward y FFT, multiply CTF, inverse y FFT. 4 kx-columns per block.
__global__ void fftcol_kernel(const float* __restrict__ ctf) {
    __shared__ float2 s[4][XSZ];
    __shared__ float2 t2[4][XSZ];
    __shared__ float2 tw[128];
    int tid  = threadIdx.x;
    int sub  = tid >> 6;
    int lane = tid & 63;
    if (tid < 128) tw[tid] = g_tw[tid];
    int b  = blockIdx.x / 33;
    int kx = (blockIdx.x % 33) * 4 + sub;
    bool act = (kx < HSPEC);
    long base = (long)b * XSZ * HSPEC + (act ? kx : 0);
    if (act) {
        for (int y = lane; y < XSZ; y += 64)
            s[sub][BREV8(y)] = g_spec[base + (long)y * HSPEC];
    } else {
        for (int y = lane; y < XSZ; y += 64)
            s[sub][y] = make_float2(0.f, 0.f);
    }
    fft256(s[sub], tw, lane, false);
    for (int ky = lane; ky < XSZ; ky += 64) {
        float c = act ? ctf[((b << 8) | ky) * HSPEC + kx] : 0.0f;
        float2 vv = s[sub][ky];
        t2[sub][BREV8(ky)] = make_float2(vv.x * c, vv.y * c);
    }
    fft256(t2[sub], tw, lane, true);
    if (act) {
        for (int y = lane; y < XSZ; y += 64)
            g_spec[base + (long)y * HSPEC] = t2[sub][y];
    }
}

// inverse row rFFT: Hermitian extend 129 -> 256, ifft, real * 1/65536.
// 4 rows per block.
__global__ void ifftrow_kernel(float* __restrict__ out) {
    __shared__ float2 s[4][XSZ];
    __shared__ float2 tw[128];
    int tid  = threadIdx.x;
    int sub  = tid >> 6;
    int lane = tid & 63;
    if (tid < 128) tw[tid] = g_tw[tid];
    int br = blockIdx.x * 4 + sub;     // b*256 + y
    for (int k = lane; k < HSPEC; k += 64) {
        float2 vv = g_spec[br*HSPEC + k];
        s[sub][BREV8(k)] = vv;
        if (k >= 1 && k <= 127) s[sub][BREV8(256 - k)] = make_float2(vv.x, -vv.y);
    }
    fft256(s[sub], tw, lane, true);
    const float scale = 1.0f / 65536.0f;
    for (int i = lane; i < XSZ; i += 64) out[br*XSZ + i] = s[sub][i].x * scale;
}

// ---------------- launch -----------------------------------------------------

extern "C" void kernel_launch(void* const* d_in, const int* in_sizes, int n_in,
                              void* d_out, int out_size) {
    const float* rows   = (const float*)d_in[0];
    const float* shifts = (const float*)d_in[1];
    const float* latent = (const float*)d_in[2];
    const float* coords = (const float*)d_in[3];
    const float* values = (const float*)d_in[4];
    const float* W0 = (const float*)d_in[5];
    const float* b0 = (const float*)d_in[6];
    const float* W1 = (const float*)d_in[7];
    const float* b1 = (const float*)d_in[8];
    const float* W2 = (const float*)d_in[9];
    const float* b2 = (const float*)d_in[10];
    const float* W3 = (const float*)d_in[11];
    const float* b3 = (const float*)d_in[12];
    const float* Wd = (const float*)d_in[13];
    const float* bd = (const float*)d_in[14];
    const float* ctf = (const float*)d_in[15];
    float* out = (float*)d_out;

    zero_kernel<<<IMG_ELEMS/4/256, 256>>>();
    prep_kernel<<<1, 128>>>(rows, shifts, latent, W0, b0, W1, b1, W2, b2, W3, b3);
    scatter_kernel<<<(NPTS + 255)/256, 256>>>(coords, values, Wd, bd);
    fftrow_kernel<<<BB*XSZ/4, 256>>>();
    fftcol_kernel<<<BB*33, 256>>>(ctf);
    ifftrow_kernel<<<BB*XSZ/4, 256>>>(out);
}

// round 5
// speedup vs baseline: 1.8799x; 1.2466x over previous
#include <cuda_runtime.h>
#include <math.h>

#define BB 16
#define LATD 8
#define NPTS 500000
#define XSZ 256
#define HSPEC 129   // XSZ/2 + 1
#define IMG_ELEMS (BB*XSZ*XSZ)

// ---------------- scratch (device globals; no allocation allowed) ----------
__device__ float  g_img[IMG_ELEMS];                 // 4 MB accumulation image
__device__ float2 g_spec[BB*XSZ*HSPEC];             // half-spectrum
__device__ float  g_params[BB][16];                 // R rows(6), shifts(2), h(8)
__device__ float2 g_tw[128];                        // exp(-2*pi*i*k/256)

// Gaussian kernel (sigma=1, radius=3), normalized (double-derived constants)
__device__ __constant__ float c_gk[7] = {
    0.0044330481f, 0.0540055826f, 0.2420362294f, 0.3990502730f,
    0.2420362294f, 0.0540055826f, 0.0044330481f
};

#define SKEW(i) ((i) + ((i) >> 5))   // bank-conflict skew for SoA smem

// ---------------- kernels ---------------------------------------------------

__global__ void zero_kernel() {
    int i = blockIdx.x * blockDim.x + threadIdx.x;
    ((float4*)g_img)[i] = make_float4(0.f, 0.f, 0.f, 0.f);
}

__global__ void prep_kernel(const float* __restrict__ rows,
                            const float* __restrict__ shifts,
                            const float* __restrict__ latent,
                            const float* __restrict__ W0, const float* __restrict__ b0,
                            const float* __restrict__ W1, const float* __restrict__ b1,
                            const float* __restrict__ W2, const float* __restrict__ b2,
                            const float* __restrict__ W3, const float* __restrict__ b3) {
    int tid = threadIdx.x;
    if (tid < 128) {
        double s, c;
        sincos(-3.14159265358979323846 * (double)tid / 128.0, &s, &c);
        g_tw[tid] = make_float2((float)c, (float)s);
    }
    int b = tid;
    if (b >= BB) return;
    // ---- FROZEN position-path arithmetic (do not modify) ----
    float rot  = rows[b*3+0];
    float tilt = rows[b*3+1];
    float psi  = rows[b*3+2];
    float ca = cosf(rot),  sa = sinf(rot);
    float cb = cosf(tilt), sb = sinf(tilt);
    float cg = cosf(psi),  sg = sinf(psi);
    float cgcb = __fmul_rn(cg, cb);
    float sgcb = __fmul_rn(sg, cb);
    g_params[b][0] = __fsub_rn(__fmul_rn(cgcb, ca), __fmul_rn(sg, sa));
    g_params[b][1] = __fadd_rn(__fmul_rn(cgcb, sa), __fmul_rn(sg, ca));
    g_params[b][2] = -__fmul_rn(cg, sb);
    g_params[b][3] = __fsub_rn(__fmul_rn(-sgcb, ca), __fmul_rn(cg, sa));
    g_params[b][4] = __fadd_rn(__fmul_rn(-sgcb, sa), __fmul_rn(cg, ca));
    g_params[b][5] = __fmul_rn(sg, sb);
    g_params[b][6] = shifts[b*2+0];
    g_params[b][7] = shifts[b*2+1];

    float h[LATD];
    #pragma unroll
    for (int j = 0; j < LATD; j++) {
        float z = b0[j];
        #pragma unroll
        for (int l = 0; l < LATD; l++) z += latent[b*LATD+l] * W0[l*LATD+j];
        h[j] = sinf(30.0f * z);
    }
    const float* Ws[3] = {W1, W2, W3};
    const float* bs[3] = {b1, b2, b3};
    for (int L = 0; L < 3; L++) {
        float t[LATD];
        #pragma unroll
        for (int j = 0; j < LATD; j++) {
            float z = bs[L][j];
            #pragma unroll
            for (int l = 0; l < LATD; l++) z += h[l] * Ws[L][l*LATD+j];
            t[j] = sinf(z);
        }
        #pragma unroll
        for (int j = 0; j < LATD; j++) h[j] += t[j];
    }
    #pragma unroll
    for (int j = 0; j < LATD; j++) g_params[b][8+j] = h[j];
}

__global__ void scatter_kernel(const float* __restrict__ coords,
                               const float* __restrict__ values,
                               const float* __restrict__ Wd,
                               const float* __restrict__ bd) {
    __shared__ float sp[BB][16];
    __shared__ float sc[768];
    int t = threadIdx.x;
    if (t < BB*16) ((float*)sp)[t] = ((const float*)g_params)[t];
    int base = blockIdx.x * 256 * 3;
    #pragma unroll
    for (int f = 0; f < 3; f++) {
        int g = base + t + f*256;
        sc[t + f*256] = (g < NPTS*3) ? coords[g] : 0.0f;
    }
    __syncthreads();

    int n = blockIdx.x * blockDim.x + t;
    if (n >= NPTS) return;

    float cx = sc[t*3+0];
    float cy = sc[t*3+1];
    float cz = sc[t*3+2];
    float v   = values[n];
    float bdn = bd[n];
    float wd[LATD];
    #pragma unroll
    for (int l = 0; l < LATD; l++) wd[l] = Wd[l*NPTS + n];

    #pragma unroll
    for (int b = 0; b < BB; b++) {
        // ---- FROZEN position-path arithmetic (do not modify) ----
        float x = __fmul_rn(sp[b][0], cx);
        x = __fmaf_rn(sp[b][1], cy, x);
        x = __fmaf_rn(sp[b][2], cz, x);
        float y = __fmul_rn(sp[b][3], cx);
        y = __fmaf_rn(sp[b][4], cy, y);
        y = __fmaf_rn(sp[b][5], cz, y);
        float fx = rintf(__fadd_rn(__fadd_rn(x, sp[b][6]), 128.0f));
        float fy = rintf(__fadd_rn(__fadd_rn(y, sp[b][7]), 128.0f));
        fx = fminf(fmaxf(fx, 0.0f), 255.0f);
        fy = fminf(fmaxf(fy, 0.0f), 255.0f);
        int ix = (int)fx;
        int iy = (int)fy;
        float dot = sp[b][8] * wd[0];
        #pragma unroll
        for (int l = 1; l < LATD; l++) dot += sp[b][8+l] * wd[l];
        float val = v + (dot + bdn);
        atomicAdd(&g_img[(b << 16) | (iy << 8) | ix], val);
    }
}

// ---- radix-4 Stockham FFT, N=256, 64 lanes per FFT, SoA smem + skew --------

template<bool INV>
__device__ __forceinline__ void fft_r4(float* RA, float* IA, float* RB, float* IB,
                                       const float2* tw, int lane) {
    float* sr = RA; float* si = IA; float* dr = RB; float* di = IB;
    #pragma unroll
    for (int st = 0; st < 4; st++) {
        const int Ns = 1 << (2*st);
        int k    = lane & (Ns - 1);
        int base = ((lane - k) << 2) + k;
        float2 w1 = tw[k << (6 - 2*st)];
        if (INV) w1.y = -w1.y;
        float w2r = w1.x*w1.x - w1.y*w1.y, w2i = 2.f*w1.x*w1.y;
        float w3r = w2r*w1.x - w2i*w1.y,  w3i = w2r*w1.y + w2i*w1.x;
        float ar  = sr[SKEW(lane)],       ai  = si[SKEW(lane)];
        float br_ = sr[SKEW(lane+64)],    bi  = si[SKEW(lane+64)];
        float cr  = sr[SKEW(lane+128)],   ci  = si[SKEW(lane+128)];
        float dr_ = sr[SKEW(lane+192)],   di_ = si[SKEW(lane+192)];
        float tbr = w1.x*br_ - w1.y*bi,   tbi = w1.x*bi  + w1.y*br_;
        float tcr = w2r*cr  - w2i*ci,     tci = w2r*ci  + w2i*cr;
        float tdr = w3r*dr_ - w3i*di_,    tdi = w3r*di_ + w3i*dr_;
        float t0r = ar + tcr,  t0i = ai + tci;
        float t1r = ar - tcr,  t1i = ai - tci;
        float t2r = tbr + tdr, t2i = tbi + tdi;
        float t3r = tbr - tdr, t3i = tbi - tdi;
        dr[SKEW(base)]      = t0r + t2r;  di[SKEW(base)]      = t0i + t2i;
        dr[SKEW(base+2*Ns)] = t0r - t2r;  di[SKEW(base+2*Ns)] = t0i - t2i;
        if (!INV) {
            dr[SKEW(base+Ns)]   = t1r + t3i;  di[SKEW(base+Ns)]   = t1i - t3r;
            dr[SKEW(base+3*Ns)] = t1r - t3i;  di[SKEW(base+3*Ns)] = t1i + t3r;
        } else {
            dr[SKEW(base+Ns)]   = t1r - t3i;  di[SKEW(base+Ns)]   = t1i + t3r;
            dr[SKEW(base+3*Ns)] = t1r + t3i;  di[SKEW(base+3*Ns)] = t1i - t3r;
        }
        __syncthreads();
        float* tp;
        tp = sr; sr = dr; dr = tp;
        tp = si; si = di; di = tp;
    }
}

// fused y-blur + x-blur + two-for-one forward row rFFT.
__global__ void fftrow_kernel() {
    __shared__ float RA[4][264], IA[4][264], RB[4][264], IB[4][264];
    __shared__ float2 tw[64];
    int tid = threadIdx.x, sub = tid >> 6, lane = tid & 63;
    if (tid < 64) tw[tid] = g_tw[tid];
    int rp = blockIdx.x * 4 + sub;        // pair index, 128 pairs per image
    int b  = rp >> 7;
    int y0 = (rp & 127) << 1;
    int y1 = y0 + 1;
    const float* imgb = g_img + (b << 16);
    for (int i = lane; i < XSZ; i += 64) {
        float a0 = 0.f, a1 = 0.f;
        #pragma unroll
        for (int d = -3; d <= 3; d++) {
            int ya = y0 + d;
            if (ya >= 0 && ya < XSZ) a0 += c_gk[d+3] * imgb[(ya << 8) + i];
            int yb = y1 + d;
            if (yb >= 0 && yb < XSZ) a1 += c_gk[d+3] * imgb[(yb << 8) + i];
        }
        RB[sub][i] = a0;
        IB[sub][i] = a1;
    }
    __syncthreads();
    for (int i = lane; i < XSZ; i += 64) {
        float a0 = 0.f, a1 = 0.f;
        #pragma unroll
        for (int d = -3; d <= 3; d++) {
            int xx = i + d;
            if (xx >= 0 && xx < XSZ) {
                a0 += c_gk[d+3] * RB[sub][xx];
                a1 += c_gk[d+3] * IB[sub][xx];
            }
        }
        RA[sub][SKEW(i)] = a0;
        IA[sub][SKEW(i)] = a1;
    }
    __syncthreads();
    fft_r4<false>(RA[sub], IA[sub], RB[sub], IB[sub], tw, lane);
    long base0 = (long)((b << 8) | y0) * HSPEC;
    long base1 = (long)((b << 8) | y1) * HSPEC;
    for (int k = lane; k <= 128; k += 64) {
        int kn = (256 - k) & 255;
        float zr = RA[sub][SKEW(k)],  zi = IA[sub][SKEW(k)];
        float nr = RA[sub][SKEW(kn)], ni = IA[sub][SKEW(kn)];
        g_spec[base0 + k] = make_float2(0.5f*(zr + nr), 0.5f*(zi - ni));
        g_spec[base1 + k] = make_float2(0.5f*(zi + ni), 0.5f*(nr - zr));
    }
}

// forward y FFT, multiply CTF, inverse y FFT. 4 kx-columns per block.
__global__ void fftcol_kernel(const float* __restrict__ ctf) {
    __shared__ float RA[4][264], IA[4][264], RB[4][264], IB[4][264];
    __shared__ float2 tw[64];
    int tid = threadIdx.x, sub = tid >> 6, lane = tid & 63;
    if (tid < 64) tw[tid] = g_tw[tid];
    int b  = blockIdx.x / 33;
    int kx = (blockIdx.x % 33) * 4 + sub;
    bool act = (kx < HSPEC);
    int kxe = act ? kx : 0;
    long base = (long)b * XSZ * HSPEC + kxe;
    for (int y = lane; y < XSZ; y += 64) {
        float2 v = g_spec[base + (long)y * HSPEC];
        RA[sub][SKEW(y)] = v.x;
        IA[sub][SKEW(y)] = v.y;
    }
    __syncthreads();
    fft_r4<false>(RA[sub], IA[sub], RB[sub], IB[sub], tw, lane);
    for (int ky = lane; ky < XSZ; ky += 64) {
        float c = ctf[((b << 8) | ky) * HSPEC + kxe];
        RA[sub][SKEW(ky)] *= c;
        IA[sub][SKEW(ky)] *= c;
    }
    __syncthreads();
    fft_r4<true>(RA[sub], IA[sub], RB[sub], IB[sub], tw, lane);
    if (act) {
        for (int y = lane; y < XSZ; y += 64)
            g_spec[base + (long)y * HSPEC] =
                make_float2(RA[sub][SKEW(y)], IA[sub][SKEW(y)]);
    }
}

// two-for-one inverse row rFFT.
// CRITICAL: irfft drops Im(h[0]) and Im(h[128]); after the CTF multiply those
// imaginary parts are O(signal) (ctf is not ky-symmetric). Zero them before
// the packed merge, else they leak across the row pair.
__global__ void ifftrow_kernel(float* __restrict__ out) {
    __shared__ float RA[4][264], IA[4][264], RB[4][264], IB[4][264];
    __shared__ float2 tw[64];
    int tid = threadIdx.x, sub = tid >> 6, lane = tid & 63;
    if (tid < 64) tw[tid] = g_tw[tid];
    int rp = blockIdx.x * 4 + sub;
    int b  = rp >> 7;
    int y0 = (rp & 127) << 1;
    int y1 = y0 + 1;
    long base0 = (long)((b << 8) | y0) * HSPEC;
    long base1 = (long)((b << 8) | y1) * HSPEC;
    for (int k = lane; k <= 128; k += 64) {
        float2 A  = g_spec[base0 + k];
        float2 Bv = g_spec[base1 + k];
        if (k == 0 || k == 128) { A.y = 0.f; Bv.y = 0.f; }   // irfft semantics
        RA[sub][SKEW(k)] = A.x - Bv.y;     // z[k] = Fa[k] + i*Fb[k]
        IA[sub][SKEW(k)] = A.y + Bv.x;
        if (k >= 1 && k <= 127) {
            int m = 256 - k;               // z[m] = conj(Fa[k]) + i*conj(Fb[k])
            RA[sub][SKEW(m)] =  A.x + Bv.y;
            IA[sub][SKEW(m)] = -A.y + Bv.x;
        }
    }
    __syncthreads();
    fft_r4<true>(RA[sub], IA[sub], RB[sub], IB[sub], tw, lane);
    const float sc = 1.0f / 65536.0f;
    float* o0 = out + ((long)((b << 8) | y0) << 8);
    float* o1 = out + ((long)((b << 8) | y1) << 8);
    for (int i = lane; i < XSZ; i += 64) {
        o0[i] = RA[sub][SKEW(i)] * sc;
        o1[i] = IA[sub][SKEW(i)] * sc;
    }
}

// ---------------- launch -----------------------------------------------------

extern "C" void kernel_launch(void* const* d_in, const int* in_sizes, int n_in,
                              void* d_out, int out_size) {
    const float* rows   = (const float*)d_in[0];
    const float* shifts = (const float*)d_in[1];
    const float* latent = (const float*)d_in[2];
    const float* coords = (const float*)d_in[3];
    const float* values = (const float*)d_in[4];
    const float* W0 = (const float*)d_in[5];
    const float* b0 = (const float*)d_in[6];
    const float* W1 = (const float*)d_in[7];
    const float* b1 = (const float*)d_in[8];
    const float* W2 = (const float*)d_in[9];
    const float* b2 = (const float*)d_in[10];
    const float* W3 = (const float*)d_in[11];
    const float* b3 = (const float*)d_in[12];
    const float* Wd = (const float*)d_in[13];
    const float* bd = (const float*)d_in[14];
    const float* ctf = (const float*)d_in[15];
    float* out = (float*)d_out;

    zero_kernel<<<IMG_ELEMS/4/256, 256>>>();
    prep_kernel<<<1, 128>>>(rows, shifts, latent, W0, b0, W1, b1, W2, b2, W3, b3);
    scatter_kernel<<<(NPTS + 255)/256, 256>>>(coords, values, Wd, bd);
    fftrow_kernel<<<BB*XSZ/2/4, 256>>>();
    fftcol_kernel<<<BB*33, 256>>>(ctf);
    ifftrow_kernel<<<BB*XSZ/2/4, 256>>>(out);
}

// round 6
// speedup vs baseline: 1.8977x; 1.0094x over previous
#include <cuda_runtime.h>
#include <math.h>

#define BB 16
#define LATD 8
#define NPTS 500000
#define XSZ 256
#define HSPEC 129   // XSZ/2 + 1
#define IMG_ELEMS (BB*XSZ*XSZ)

// ---------------- scratch (device globals; no allocation allowed) ----------
__device__ float  g_img[IMG_ELEMS];                  // 4 MB accumulation image
__device__ float2 g_spec[BB*HSPEC*XSZ];              // spectrum, layout [b][kx][y]
__device__ float  g_ctft[BB*HSPEC*XSZ];              // ctf transposed [b][kx][ky]
__device__ float  g_params[BB][16];                  // R rows(6), shifts(2), h(8)
__device__ float2 g_tw[128];                         // exp(-2*pi*i*k/256)

// Gaussian kernel (sigma=1, radius=3), normalized (double-derived constants)
__device__ __constant__ float c_gk[7] = {
    0.0044330481f, 0.0540055826f, 0.2420362294f, 0.3990502730f,
    0.2420362294f, 0.0540055826f, 0.0044330481f
};

#define SKEW(i) ((i) + ((i) >> 5))   // bank-conflict skew for SoA smem

// ---------------- zero + prep (merged) --------------------------------------

__global__ void zero_prep_kernel(const float* __restrict__ rows,
                                 const float* __restrict__ shifts,
                                 const float* __restrict__ latent,
                                 const float* __restrict__ W0, const float* __restrict__ b0,
                                 const float* __restrict__ W1, const float* __restrict__ b1,
                                 const float* __restrict__ W2, const float* __restrict__ b2,
                                 const float* __restrict__ W3, const float* __restrict__ b3) {
    int i = blockIdx.x * blockDim.x + threadIdx.x;
    ((float4*)g_img)[i] = make_float4(0.f, 0.f, 0.f, 0.f);
    if (blockIdx.x != 0) return;
    int tid = threadIdx.x;
    if (tid < 128) {
        double s, c;
        sincos(-3.14159265358979323846 * (double)tid / 128.0, &s, &c);
        g_tw[tid] = make_float2((float)c, (float)s);
    }
    int b = tid;
    if (b >= BB) return;
    // ---- FROZEN position-path arithmetic (do not modify) ----
    float rot  = rows[b*3+0];
    float tilt = rows[b*3+1];
    float psi  = rows[b*3+2];
    float ca = cosf(rot),  sa = sinf(rot);
    float cb = cosf(tilt), sb = sinf(tilt);
    float cg = cosf(psi),  sg = sinf(psi);
    float cgcb = __fmul_rn(cg, cb);
    float sgcb = __fmul_rn(sg, cb);
    g_params[b][0] = __fsub_rn(__fmul_rn(cgcb, ca), __fmul_rn(sg, sa));
    g_params[b][1] = __fadd_rn(__fmul_rn(cgcb, sa), __fmul_rn(sg, ca));
    g_params[b][2] = -__fmul_rn(cg, sb);
    g_params[b][3] = __fsub_rn(__fmul_rn(-sgcb, ca), __fmul_rn(cg, sa));
    g_params[b][4] = __fadd_rn(__fmul_rn(-sgcb, sa), __fmul_rn(cg, ca));
    g_params[b][5] = __fmul_rn(sg, sb);
    g_params[b][6] = shifts[b*2+0];
    g_params[b][7] = shifts[b*2+1];

    float h[LATD];
    #pragma unroll
    for (int j = 0; j < LATD; j++) {
        float z = b0[j];
        #pragma unroll
        for (int l = 0; l < LATD; l++) z += latent[b*LATD+l] * W0[l*LATD+j];
        h[j] = sinf(30.0f * z);
    }
    const float* Ws[3] = {W1, W2, W3};
    const float* bs[3] = {b1, b2, b3};
    for (int L = 0; L < 3; L++) {
        float t[LATD];
        #pragma unroll
        for (int j = 0; j < LATD; j++) {
            float z = bs[L][j];
            #pragma unroll
            for (int l = 0; l < LATD; l++) z += h[l] * Ws[L][l*LATD+j];
            t[j] = sinf(z);
        }
        #pragma unroll
        for (int j = 0; j < LATD; j++) h[j] += t[j];
    }
    #pragma unroll
    for (int j = 0; j < LATD; j++) g_params[b][8+j] = h[j];
}

// ---------------- ctf transpose: [b][ky][kx] -> [b][kx][ky] -----------------

__global__ void ctft_kernel(const float* __restrict__ ctf) {
    __shared__ float t[32][33];
    int tx = threadIdx.x, ty = threadIdx.y;
    int bxk = blockIdx.x;        // kx tile (0..4)
    int byk = blockIdx.y;        // ky tile (0..7)
    int b   = blockIdx.z;
    int kx = bxk*32 + tx;
    #pragma unroll
    for (int j = 0; j < 4; j++) {
        int ky = byk*32 + ty + j*8;
        if (kx < HSPEC) t[ty + j*8][tx] = ctf[((b << 8) + ky)*HSPEC + kx];
    }
    __syncthreads();
    #pragma unroll
    for (int j = 0; j < 4; j++) {
        int kxo = bxk*32 + ty + j*8;
        int kyo = byk*32 + tx;
        if (kxo < HSPEC) g_ctft[((b*HSPEC + kxo) << 8) + kyo] = t[tx][ty + j*8];
    }
}

// ---------------- scatter ----------------------------------------------------

__global__ void scatter_kernel(const float* __restrict__ coords,
                               const float* __restrict__ values,
                               const float* __restrict__ Wd,
                               const float* __restrict__ bd) {
    __shared__ float sp[BB][16];
    __shared__ float sc[768];
    int t = threadIdx.x;
    if (t < BB*16) ((float*)sp)[t] = ((const float*)g_params)[t];
    int base = blockIdx.x * 256 * 3;
    #pragma unroll
    for (int f = 0; f < 3; f++) {
        int g = base + t + f*256;
        sc[t + f*256] = (g < NPTS*3) ? coords[g] : 0.0f;
    }
    __syncthreads();

    int n = blockIdx.x * blockDim.x + t;
    if (n >= NPTS) return;

    float cx = sc[t*3+0];
    float cy = sc[t*3+1];
    float cz = sc[t*3+2];
    float v   = values[n];
    float bdn = bd[n];
    float wd[LATD];
    #pragma unroll
    for (int l = 0; l < LATD; l++) wd[l] = Wd[l*NPTS + n];

    #pragma unroll
    for (int b = 0; b < BB; b++) {
        // ---- FROZEN position-path arithmetic (do not modify) ----
        float x = __fmul_rn(sp[b][0], cx);
        x = __fmaf_rn(sp[b][1], cy, x);
        x = __fmaf_rn(sp[b][2], cz, x);
        float y = __fmul_rn(sp[b][3], cx);
        y = __fmaf_rn(sp[b][4], cy, y);
        y = __fmaf_rn(sp[b][5], cz, y);
        float fx = rintf(__fadd_rn(__fadd_rn(x, sp[b][6]), 128.0f));
        float fy = rintf(__fadd_rn(__fadd_rn(y, sp[b][7]), 128.0f));
        fx = fminf(fmaxf(fx, 0.0f), 255.0f);
        fy = fminf(fmaxf(fy, 0.0f), 255.0f);
        int ix = (int)fx;
        int iy = (int)fy;
        float dot = sp[b][8] * wd[0];
        #pragma unroll
        for (int l = 1; l < LATD; l++) dot += sp[b][8+l] * wd[l];
        float val = v + (dot + bdn);
        atomicAdd(&g_img[(b << 16) | (iy << 8) | ix], val);
    }
}

// ---- radix-4 Stockham FFT, N=256, 64 lanes per FFT, SoA smem + skew --------

template<bool INV>
__device__ __forceinline__ void fft_r4(float* RA, float* IA, float* RB, float* IB,
                                       const float2* tw, int lane) {
    float* sr = RA; float* si = IA; float* dr = RB; float* di = IB;
    #pragma unroll
    for (int st = 0; st < 4; st++) {
        const int Ns = 1 << (2*st);
        int k    = lane & (Ns - 1);
        int base = ((lane - k) << 2) + k;
        float2 w1 = tw[k << (6 - 2*st)];
        if (INV) w1.y = -w1.y;
        float w2r = w1.x*w1.x - w1.y*w1.y, w2i = 2.f*w1.x*w1.y;
        float w3r = w2r*w1.x - w2i*w1.y,  w3i = w2r*w1.y + w2i*w1.x;
        float ar  = sr[SKEW(lane)],       ai  = si[SKEW(lane)];
        float br_ = sr[SKEW(lane+64)],    bi  = si[SKEW(lane+64)];
        float cr  = sr[SKEW(lane+128)],   ci  = si[SKEW(lane+128)];
        float dr_ = sr[SKEW(lane+192)],   di_ = si[SKEW(lane+192)];
        float tbr = w1.x*br_ - w1.y*bi,   tbi = w1.x*bi  + w1.y*br_;
        float tcr = w2r*cr  - w2i*ci,     tci = w2r*ci  + w2i*cr;
        float tdr = w3r*dr_ - w3i*di_,    tdi = w3r*di_ + w3i*dr_;
        float t0r = ar + tcr,  t0i = ai + tci;
        float t1r = ar - tcr,  t1i = ai - tci;
        float t2r = tbr + tdr, t2i = tbi + tdi;
        float t3r = tbr - tdr, t3i = tbi - tdi;
        dr[SKEW(base)]      = t0r + t2r;  di[SKEW(base)]      = t0i + t2i;
        dr[SKEW(base+2*Ns)] = t0r - t2r;  di[SKEW(base+2*Ns)] = t0i - t2i;
        if (!INV) {
            dr[SKEW(base+Ns)]   = t1r + t3i;  di[SKEW(base+Ns)]   = t1i - t3r;
            dr[SKEW(base+3*Ns)] = t1r - t3i;  di[SKEW(base+3*Ns)] = t1i + t3r;
        } else {
            dr[SKEW(base+Ns)]   = t1r - t3i;  di[SKEW(base+Ns)]   = t1i + t3r;
            dr[SKEW(base+3*Ns)] = t1r + t3i;  di[SKEW(base+3*Ns)] = t1i - t3r;
        }
        __syncthreads();
        float* tp;
        tp = sr; sr = dr; dr = tp;
        tp = si; si = di; di = tp;
    }
}

// fused y-blur + x-blur + two-for-one forward row rFFT.
// Block = 8-row tile of one image (4 pairs). Stages the 14-row blur window
// once in smem, and stages spectrum output through a tile for coalesced
// writes to the [b][kx][y] layout.
__global__ void fftrow_kernel() {
    __shared__ float  win[14][XSZ];
    __shared__ float  RA[4][264], IA[4][264], RB[4][264], IB[4][264];
    __shared__ float2 st[HSPEC][9];
    __shared__ float2 tw[64];
    int tid = threadIdx.x, sub = tid >> 6, lane = tid & 63;
    if (tid < 64) tw[tid] = g_tw[tid];
    int b  = blockIdx.x >> 5;
    int y0 = (blockIdx.x & 31) << 3;       // tile rows y0..y0+7
    const float* imgb = g_img + (b << 16);
    // stage window rows y0-3 .. y0+10 (coalesced float4)
    for (int idx = tid; idx < 14*64; idx += 256) {
        int r = idx >> 6, x4 = idx & 63;
        int wr = y0 - 3 + r;
        if (wr >= 0 && wr < XSZ)
            ((float4*)win[r])[x4] = ((const float4*)(imgb + (wr << 8)))[x4];
    }
    __syncthreads();
    int yp0 = y0 + (sub << 1);             // pair rows
    int yp1 = yp0 + 1;
    // y-blur from window (same order/guards as before)
    for (int i = lane; i < XSZ; i += 64) {
        float a0 = 0.f, a1 = 0.f;
        #pragma unroll
        for (int d = -3; d <= 3; d++) {
            int ya = yp0 + d;
            if (ya >= 0 && ya < XSZ) a0 += c_gk[d+3] * win[(sub << 1) + d + 3][i];
            int yb = yp1 + d;
            if (yb >= 0 && yb < XSZ) a1 += c_gk[d+3] * win[(sub << 1) + d + 4][i];
        }
        RB[sub][i] = a0;
        IB[sub][i] = a1;
    }
    __syncthreads();
    for (int i = lane; i < XSZ; i += 64) {
        float a0 = 0.f, a1 = 0.f;
        #pragma unroll
        for (int d = -3; d <= 3; d++) {
            int xx = i + d;
            if (xx >= 0 && xx < XSZ) {
                a0 += c_gk[d+3] * RB[sub][xx];
                a1 += c_gk[d+3] * IB[sub][xx];
            }
        }
        RA[sub][SKEW(i)] = a0;
        IA[sub][SKEW(i)] = a1;
    }
    __syncthreads();
    fft_r4<false>(RA[sub], IA[sub], RB[sub], IB[sub], tw, lane);
    // split packed spectrum into the staging tile
    for (int k = lane; k <= 128; k += 64) {
        int kn = (256 - k) & 255;
        float zr = RA[sub][SKEW(k)],  zi = IA[sub][SKEW(k)];
        float nr = RA[sub][SKEW(kn)], ni = IA[sub][SKEW(kn)];
        st[k][(sub << 1) + 0] = make_float2(0.5f*(zr + nr), 0.5f*(zi - ni));
        st[k][(sub << 1) + 1] = make_float2(0.5f*(zi + ni), 0.5f*(nr - zr));
    }
    __syncthreads();
    // coalesced write-out to [b][kx][y] layout
    for (int idx = tid; idx < HSPEC*8; idx += 256) {
        int k = idx >> 3, yl = idx & 7;
        g_spec[((b*HSPEC + k) << 8) + y0 + yl] = st[k][yl];
    }
}

// forward y FFT, multiply CTF, inverse y FFT. 4 kx-columns per block.
// [b][kx][y] layout -> fully coalesced loads/stores.
__global__ void fftcol_kernel() {
    __shared__ float RA[4][264], IA[4][264], RB[4][264], IB[4][264];
    __shared__ float2 tw[64];
    int tid = threadIdx.x, sub = tid >> 6, lane = tid & 63;
    if (tid < 64) tw[tid] = g_tw[tid];
    int b  = blockIdx.x / 33;
    int kx = (blockIdx.x % 33) * 4 + sub;
    bool act = (kx < HSPEC);
    int kxe = act ? kx : 0;
    int base = (b*HSPEC + kxe) << 8;
    for (int y = lane; y < XSZ; y += 64) {
        float2 v = g_spec[base + y];
        RA[sub][SKEW(y)] = v.x;
        IA[sub][SKEW(y)] = v.y;
    }
    __syncthreads();
    fft_r4<false>(RA[sub], IA[sub], RB[sub], IB[sub], tw, lane);
    for (int ky = lane; ky < XSZ; ky += 64) {
        float c = g_ctft[base + ky];
        RA[sub][SKEW(ky)] *= c;
        IA[sub][SKEW(ky)] *= c;
    }
    __syncthreads();
    fft_r4<true>(RA[sub], IA[sub], RB[sub], IB[sub], tw, lane);
    if (act) {
        for (int y = lane; y < XSZ; y += 64)
            g_spec[base + y] = make_float2(RA[sub][SKEW(y)], IA[sub][SKEW(y)]);
    }
}

// two-for-one inverse row rFFT. Block = 8-row tile; staged coalesced loads
// from the [b][kx][y] layout.
// irfft drops Im(h[0]) and Im(h[128]) — zero them before the packed merge.
__global__ void ifftrow_kernel(float* __restrict__ out) {
    __shared__ float  RA[4][264], IA[4][264], RB[4][264], IB[4][264];
    __shared__ float2 st[HSPEC][9];
    __shared__ float2 tw[64];
    int tid = threadIdx.x, sub = tid >> 6, lane = tid & 63;
    if (tid < 64) tw[tid] = g_tw[tid];
    int b  = blockIdx.x >> 5;
    int y0 = (blockIdx.x & 31) << 3;
    // staged coalesced load of the 129 x 8 tile
    for (int idx = tid; idx < HSPEC*8; idx += 256) {
        int k = idx >> 3, yl = idx & 7;
        st[k][yl] = g_spec[((b*HSPEC + k) << 8) + y0 + yl];
    }
    __syncthreads();
    for (int k = lane; k <= 128; k += 64) {
        float2 A  = st[k][(sub << 1) + 0];
        float2 Bv = st[k][(sub << 1) + 1];
        if (k == 0 || k == 128) { A.y = 0.f; Bv.y = 0.f; }   // irfft semantics
        RA[sub][SKEW(k)] = A.x - Bv.y;     // z[k] = Fa[k] + i*Fb[k]
        IA[sub][SKEW(k)] = A.y + Bv.x;
        if (k >= 1 && k <= 127) {
            int m = 256 - k;               // z[m] = conj(Fa[k]) + i*conj(Fb[k])
            RA[sub][SKEW(m)] =  A.x + Bv.y;
            IA[sub][SKEW(m)] = -A.y + Bv.x;
        }
    }
    __syncthreads();
    fft_r4<true>(RA[sub], IA[sub], RB[sub], IB[sub], tw, lane);
    const float sc = 1.0f / 65536.0f;
    int yp0 = y0 + (sub << 1);
    float* o0 = out + ((long)((b << 8) | yp0) << 8);
    float* o1 = o0 + XSZ;
    for (int i = lane; i < XSZ; i += 64) {
        o0[i] = RA[sub][SKEW(i)] * sc;
        o1[i] = IA[sub][SKEW(i)] * sc;
    }
}

// ---------------- launch -----------------------------------------------------

extern "C" void kernel_launch(void* const* d_in, const int* in_sizes, int n_in,
                              void* d_out, int out_size) {
    const float* rows   = (const float*)d_in[0];
    const float* shifts = (const float*)d_in[1];
    const float* latent = (const float*)d_in[2];
    const float* coords = (const float*)d_in[3];
    const float* values = (const float*)d_in[4];
    const float* W0 = (const float*)d_in[5];
    const float* b0 = (const float*)d_in[6];
    const float* W1 = (const float*)d_in[7];
    const float* b1 = (const float*)d_in[8];
    const float* W2 = (const float*)d_in[9];
    const float* b2 = (const float*)d_in[10];
    const float* W3 = (const float*)d_in[11];
    const float* b3 = (const float*)d_in[12];
    const float* Wd = (const float*)d_in[13];
    const float* bd = (const float*)d_in[14];
    const float* ctf = (const float*)d_in[15];
    float* out = (float*)d_out;

    zero_prep_kernel<<<IMG_ELEMS/4/256, 256>>>(rows, shifts, latent,
                                               W0, b0, W1, b1, W2, b2, W3, b3);
    ctft_kernel<<<dim3(5, 8, BB), dim3(32, 8)>>>(ctf);
    scatter_kernel<<<(NPTS + 255)/256, 256>>>(coords, values, Wd, bd);
    fftrow_kernel<<<BB*32, 256>>>();
    fftcol_kernel<<<BB*33, 256>>>();
    ifftrow_kernel<<<BB*32, 256>>>(out);
}